// round 13
// baseline (speedup 1.0000x reference)
#include <cuda_runtime.h>

#define FDIM 128
#define KH 5
#define NMAX 100000
#define EMAX 1600000
#define NBMAX 128
#define BN_EPS 1e-5f

typedef unsigned long long u64;

// ---------------- device scratch (static, no allocs) ----------------
__device__ float g_h[(size_t)NMAX * FDIM];   // x + agg  (51.2 MB)
__device__ float g_y[(size_t)NMAX * FDIM];   // y1       (51.2 MB)
__device__ u64   g_epack[EMAX];              // (w_bits<<32)|col per CSR slot
__device__ int   g_cnt[NMAX];                // per-node in-degree
__device__ int   g_rs[NMAX];                 // CSR row start
__device__ int   g_cur[NMAX];                // fill cursor -> row end
__device__ int   g_bsum[NBMAX], g_boff[NBMAX];
__device__ int   g_ctr[2];                   // GEMM band-steal counters
__device__ float g_hopw[8];
__device__ float g_st1[256];                 // [0:128) colsum, [128:256) colsumsq
__device__ float g_st2[256];

// ---------------- f32x2 helpers ----------------
__device__ __forceinline__ u64 pk2(float lo, float hi) {
    u64 r;
    asm("mov.b64 %0, {%1, %2};" : "=l"(r) : "f"(lo), "f"(hi));
    return r;
}
__device__ __forceinline__ float2 upk2(u64 v) {
    float2 r;
    asm("mov.b64 {%0, %1}, %2;" : "=f"(r.x), "=f"(r.y) : "l"(v));
    return r;
}
#define FMA2(d, a, b) asm("fma.rn.f32x2 %0, %1, %2, %0;" : "+l"(d) : "l"(a), "l"(b))

// ---------------- prep: zero cnt + stats + counters + softmax ----------------
__global__ void k_prep0(const float* __restrict__ hop_coef, int n) {
    int i = blockIdx.x * blockDim.x + threadIdx.x;
    if (i < n) g_cnt[i] = 0;
    if (blockIdx.x == 0) {
        if (threadIdx.x < 256) { g_st1[threadIdx.x] = 0.f; g_st2[threadIdx.x] = 0.f; }
        if (threadIdx.x == 0) {
            g_ctr[0] = 0;
            g_ctr[1] = 0;
            float v[KH];
            float m = -1e30f;
            for (int q = 0; q < KH; q++) { v[q] = hop_coef[q]; m = fmaxf(m, v[q]); }
            float s = 0.f;
            for (int q = 0; q < KH; q++) { v[q] = expf(v[q] - m); s += v[q]; }
            float inv = 1.f / s;
            for (int q = 0; q < KH; q++) g_hopw[q] = v[q] * inv;
        }
    }
}

// ---------------- CSR build ----------------
__global__ void k_hist(const int* __restrict__ ei, const int* __restrict__ ew, int E) {
    int e = blockIdx.x * blockDim.x + threadIdx.x;
    if (e >= E) return;
    int d = ew[e];
    if (d < 1 || d > KH) return;
    atomicAdd(&g_cnt[ei[e]], 1);
}

__global__ void k_scan1(int n) {   // 1024 threads/block, Hillis-Steele
    __shared__ int sh[1024];
    int i = blockIdx.x * 1024 + threadIdx.x;
    int v = (i < n) ? g_cnt[i] : 0;
    sh[threadIdx.x] = v;
    __syncthreads();
    for (int off = 1; off < 1024; off <<= 1) {
        int t = (threadIdx.x >= off) ? sh[threadIdx.x - off] : 0;
        __syncthreads();
        sh[threadIdx.x] += t;
        __syncthreads();
    }
    if (i < n) g_rs[i] = sh[threadIdx.x] - v;        // exclusive
    if (threadIdx.x == 1023) g_bsum[blockIdx.x] = sh[1023];
}

__global__ void k_scan2(int nb) {  // one block, parallel scan over block sums
    __shared__ int sh[NBMAX];
    int t = threadIdx.x;
    int v = (t < nb) ? g_bsum[t] : 0;
    sh[t] = v;
    __syncthreads();
    #pragma unroll
    for (int off = 1; off < NBMAX; off <<= 1) {
        int u = (t >= off) ? sh[t - off] : 0;
        __syncthreads();
        sh[t] += u;
        __syncthreads();
    }
    if (t < nb) g_boff[t] = sh[t] - v;               // exclusive
}

__global__ void k_scan3(int n) {
    int i = blockIdx.x * 1024 + threadIdx.x;
    if (i < n) {
        int s = g_rs[i] + g_boff[blockIdx.x];
        g_rs[i] = s;
        g_cur[i] = s;
    }
}

__global__ void k_edges(const int* __restrict__ ei, const int* __restrict__ ew, int E) {
    int e = blockIdx.x * blockDim.x + threadIdx.x;
    if (e >= E) return;
    int d = ew[e];
    if (d < 1 || d > KH) return;
    int r = ei[e];
    int c = ei[E + e];
    float w = g_hopw[d - 1];
    int pos = atomicAdd(&g_cur[r], 1);
    g_epack[pos] = ((u64)__float_as_uint(w) << 32) | (unsigned)c;
}

// ---------------- aggregate: warp per node, h = x[node] + sum(w * x[col]) ----------------
__global__ void k_aggr(const float4* __restrict__ x4, int n) {
    int node = (blockIdx.x * blockDim.x + threadIdx.x) >> 5;
    int lane = threadIdx.x & 31;
    if (node >= n) return;
    int s = g_rs[node], e = g_cur[node];
    float4 acc = __ldg(&x4[(size_t)node * 32 + lane]);
    for (int base = s; base < e; base += 32) {
        int m = min(32, e - base);
        u64 p = (lane < m) ? g_epack[base + lane] : 0ULL;
        #pragma unroll 4
        for (int j = 0; j < 32; j++) {
            if (j >= m) break;
            u64 pj = __shfl_sync(0xffffffffu, p, j);
            int c = (int)(unsigned)pj;
            float w = __uint_as_float((unsigned)(pj >> 32));
            float4 v = __ldg(&x4[(size_t)c * 32 + lane]);
            acc.x = fmaf(w, v.x, acc.x);
            acc.y = fmaf(w, v.y, acc.y);
            acc.z = fmaf(w, v.z, acc.z);
            acc.w = fmaf(w, v.w, acc.w);
        }
    }
    ((float4*)g_h)[(size_t)node * 32 + lane] = acc;
}

// ---------------- GEMM: warp-autonomous 8-row band stealing ----------------
// PHASE 1: A = g_h, Y = g_y, stats -> g_st1
// PHASE 2: A = relu(a1*g_y + c1) (a1/c1 computed per block from g_st1), Y = OutY, stats -> g_st2
// Each warp: steal band b (rows b*8..b*8+7), stage its own 4KB At slice,
// run mainloop (identical instruction mix to R8), epilogue. No block barriers.
template <int PHASE>
__global__ void __launch_bounds__(256) k_gemm(const float* __restrict__ W,
                                              const float* __restrict__ gamma,
                                              const float* __restrict__ beta,
                                              float* __restrict__ OutY,
                                              int n, int nbands, float invN) {
    const float* A = (PHASE == 1) ? g_h : g_y;
    float* Y       = (PHASE == 1) ? g_y : OutY;

    __shared__ __align__(16) float Ws[FDIM * 128];   // [k][c]  64 KB
    __shared__ __align__(16) float At[8 * 1024];     // 8 warps x (128k x 8r) 32 KB
    __shared__ float bn[256];                        // BN1 scale/shift (phase 2)

    int tid = threadIdx.x, lane = tid & 31, wid = tid >> 5;

    // stage W (coalesced)
    const float4* W4 = (const float4*)W;
    float4* Ws4 = (float4*)Ws;
    #pragma unroll 4
    for (int i = tid; i < FDIM * 32; i += 256) Ws4[i] = W4[i];

    if (PHASE == 2 && tid < 128) {
        float mean = g_st1[tid] * invN;
        float var = g_st1[tid + 128] * invN - mean * mean;
        float s = gamma[tid] * rsqrtf(var + BN_EPS);
        bn[tid] = s;
        bn[tid + 128] = beta[tid] - mean * s;
    }
    __syncthreads();   // only block barrier in the kernel

    float* At_w = At + wid * 1024;
    int sr = lane >> 2;        // staging row within band (0..7)
    int sc0 = lane & 3;        // staging c4 base
    const float4* A4 = (const float4*)A;

    float cs[4] = {0.f, 0.f, 0.f, 0.f};   // stats accumulated across bands
    float cq[4] = {0.f, 0.f, 0.f, 0.f};

    while (true) {
        int b = 0;
        if (lane == 0) b = atomicAdd(&g_ctr[PHASE - 1], 1);
        b = __shfl_sync(0xffffffffu, b, 0);
        if (b >= nbands) break;
        int row0 = b * 8;

        // stage this warp's 8 rows x 128 k (transposed At_w[k][r])
        #pragma unroll
        for (int j = 0; j < 8; j++) {
            int c4 = sc0 + 4 * j;
            int grow = row0 + sr;
            float4 v = make_float4(0.f, 0.f, 0.f, 0.f);
            if (grow < n) {
                v = A4[(size_t)grow * 32 + c4];
                if (PHASE == 2) {
                    float4 a = *(const float4*)&bn[c4 * 4];
                    float4 c = *(const float4*)&bn[128 + c4 * 4];
                    v.x = fmaxf(fmaf(a.x, v.x, c.x), 0.f);
                    v.y = fmaxf(fmaf(a.y, v.y, c.y), 0.f);
                    v.z = fmaxf(fmaf(a.z, v.z, c.z), 0.f);
                    v.w = fmaxf(fmaf(a.w, v.w, c.w), 0.f);
                }
            }
            int k0 = c4 * 4;
            At_w[(k0 + 0) * 8 + sr] = v.x;
            At_w[(k0 + 1) * 8 + sr] = v.y;
            At_w[(k0 + 2) * 8 + sr] = v.z;
            At_w[(k0 + 3) * 8 + sr] = v.w;
        }
        __syncwarp();

        u64 acc[4][4];
        #pragma unroll
        for (int p = 0; p < 4; p++)
            #pragma unroll
            for (int c = 0; c < 4; c++) acc[p][c] = 0ULL;

        #pragma unroll 4
        for (int k = 0; k < FDIM; k++) {
            float4 wv = Ws4[k * 32 + lane];                 // LDS.128
            u64 w0 = pk2(wv.x, wv.x);
            u64 w1 = pk2(wv.y, wv.y);
            u64 w2 = pk2(wv.z, wv.z);
            u64 w3 = pk2(wv.w, wv.w);
            const ulonglong2* ak = (const ulonglong2*)&At_w[k * 8];  // broadcast
            ulonglong2 q01 = ak[0];
            ulonglong2 q23 = ak[1];
            u64 a0 = q01.x, a1 = q01.y, a2 = q23.x, a3 = q23.y;
            FMA2(acc[0][0], a0, w0); FMA2(acc[0][1], a0, w1);
            FMA2(acc[0][2], a0, w2); FMA2(acc[0][3], a0, w3);
            FMA2(acc[1][0], a1, w0); FMA2(acc[1][1], a1, w1);
            FMA2(acc[1][2], a1, w2); FMA2(acc[1][3], a1, w3);
            FMA2(acc[2][0], a2, w0); FMA2(acc[2][1], a2, w1);
            FMA2(acc[2][2], a2, w2); FMA2(acc[2][3], a2, w3);
            FMA2(acc[3][0], a3, w0); FMA2(acc[3][1], a3, w1);
            FMA2(acc[3][2], a3, w2); FMA2(acc[3][3], a3, w3);
        }

        // epilogue: store Y, accumulate stats in registers
        #pragma unroll
        for (int p = 0; p < 4; p++) {
            float2 c0 = upk2(acc[p][0]);
            float2 c1 = upk2(acc[p][1]);
            float2 c2 = upk2(acc[p][2]);
            float2 c3 = upk2(acc[p][3]);
            int r_lo = row0 + 2 * p;
            int r_hi = r_lo + 1;
            if (r_lo < n) {
                float4 o = make_float4(c0.x, c1.x, c2.x, c3.x);
                ((float4*)Y)[(size_t)r_lo * 32 + lane] = o;
                cs[0] += o.x; cs[1] += o.y; cs[2] += o.z; cs[3] += o.w;
                cq[0] += o.x * o.x; cq[1] += o.y * o.y;
                cq[2] += o.z * o.z; cq[3] += o.w * o.w;
            }
            if (r_hi < n) {
                float4 o = make_float4(c0.y, c1.y, c2.y, c3.y);
                ((float4*)Y)[(size_t)r_hi * 32 + lane] = o;
                cs[0] += o.x; cs[1] += o.y; cs[2] += o.z; cs[3] += o.w;
                cq[0] += o.x * o.x; cq[1] += o.y * o.y;
                cq[2] += o.z * o.z; cq[3] += o.w * o.w;
            }
        }
        __syncwarp();   // mainloop reads done before next band overwrites At_w
    }

    // drain stats once per thread
    float* gst = (PHASE == 1) ? g_st1 : g_st2;
    #pragma unroll
    for (int c = 0; c < 4; c++) {
        atomicAdd(&gst[lane * 4 + c], cs[c]);
        atomicAdd(&gst[128 + lane * 4 + c], cq[c]);
    }
}

// ---------------- final: BN2 computed inline + ReLU in place on d_out ----------------
__global__ void k_final(float4* __restrict__ y,
                        const float* __restrict__ gamma,
                        const float* __restrict__ beta,
                        float invN, int n4) {
    int idx0 = blockIdx.x * blockDim.x + threadIdx.x;
    int c4 = idx0 & 31;   // constant per thread: stride (2048*256) divisible by 32
    float4 a, b;
    {
        float* pa = (float*)&a;
        float* pb = (float*)&b;
        #pragma unroll
        for (int q = 0; q < 4; q++) {
            int col = c4 * 4 + q;
            float mean = g_st2[col] * invN;
            float var = g_st2[col + 128] * invN - mean * mean;
            float s = __ldg(&gamma[col]) * rsqrtf(var + BN_EPS);
            pa[q] = s;
            pb[q] = __ldg(&beta[col]) - mean * s;
        }
    }
    for (int i = idx0; i < n4; i += gridDim.x * blockDim.x) {
        float4 v = y[i];
        v.x = fmaxf(fmaf(a.x, v.x, b.x), 0.f);
        v.y = fmaxf(fmaf(a.y, v.y, b.y), 0.f);
        v.z = fmaxf(fmaf(a.z, v.z, b.z), 0.f);
        v.w = fmaxf(fmaf(a.w, v.w, b.w), 0.f);
        y[i] = v;
    }
}

// ---------------- launcher ----------------
extern "C" void kernel_launch(void* const* d_in, const int* in_sizes, int n_in,
                              void* d_out, int out_size) {
    const float* x    = (const float*)d_in[0];   // [N,128]
    const int*   ei   = (const int*)  d_in[1];   // [2,E]
    const int*   ew   = (const int*)  d_in[2];   // [E]
    const float* hop  = (const float*)d_in[3];   // [5]
    const float* W1   = (const float*)d_in[4];   // [128,128]
    const float* g1   = (const float*)d_in[6];
    const float* be1  = (const float*)d_in[7];
    const float* W2   = (const float*)d_in[8];
    const float* g2   = (const float*)d_in[10];
    const float* be2  = (const float*)d_in[11];
    float* out = (float*)d_out;

    int n = in_sizes[0] / FDIM;   // 100000
    int E = in_sizes[2];          // 1600000
    int n4 = n * 32;
    float invN = 1.f / (float)n;
    int nb = (n + 1023) / 1024;   // scan blocks (98)
    int nbands = (n + 7) / 8;     // 12500

    k_prep0<<<(n + 255) / 256, 256>>>(hop, n);
    k_hist<<<(E + 255) / 256, 256>>>(ei, ew, E);
    k_scan1<<<nb, 1024>>>(n);
    k_scan2<<<1, NBMAX>>>(nb);
    k_scan3<<<nb, 1024>>>(n);
    k_edges<<<(E + 255) / 256, 256>>>(ei, ew, E);
    k_aggr<<<(n * 32 + 255) / 256, 256>>>((const float4*)x, n);

    k_gemm<1><<<296, 256>>>(W1, g1, be1, nullptr, n, nbands, invN);
    k_gemm<2><<<296, 256>>>(W2, g1, be1, out, n, nbands, invN);
    k_final<<<2048, 256>>>((float4*)out, g2, be2, invN, n4);
}

// round 14
// speedup vs baseline: 1.5127x; 1.5127x over previous
#include <cuda_runtime.h>

#define FDIM 128
#define KH 5
#define NMAX 100000
#define EMAX 1600000
#define NBMAX 128
#define BN_EPS 1e-5f

typedef unsigned long long u64;

// ---------------- device scratch (static, no allocs) ----------------
__device__ float g_h[(size_t)NMAX * FDIM];   // x + agg  (51.2 MB)
__device__ float g_y[(size_t)NMAX * FDIM];   // y1       (51.2 MB)
__device__ u64   g_epack[EMAX];              // (w_bits<<32)|col per CSR slot
__device__ int   g_cnt[NMAX];                // per-node in-degree
__device__ int   g_rs[NMAX];                 // CSR row start
__device__ int   g_cur[NMAX];                // fill cursor -> row end
__device__ int   g_bsum[NBMAX], g_boff[NBMAX];
__device__ float g_hopw[8];
__device__ float g_st1[256];                 // [0:128) colsum, [128:256) colsumsq
__device__ float g_st2[256];
__device__ float g_a1[FDIM], g_c1[FDIM];     // BN1 fused scale/shift
__device__ float g_a2[FDIM], g_c2[FDIM];     // BN2 fused scale/shift

// ---------------- f32x2 helpers ----------------
__device__ __forceinline__ u64 pk2(float lo, float hi) {
    u64 r;
    asm("mov.b64 %0, {%1, %2};" : "=l"(r) : "f"(lo), "f"(hi));
    return r;
}
__device__ __forceinline__ float2 upk2(u64 v) {
    float2 r;
    asm("mov.b64 {%0, %1}, %2;" : "=f"(r.x), "=f"(r.y) : "l"(v));
    return r;
}
#define FMA2(d, a, b) asm("fma.rn.f32x2 %0, %1, %2, %0;" : "+l"(d) : "l"(a), "l"(b))

// ---------------- prep: zero cnt + stats + softmax ----------------
__global__ void k_prep0(const float* __restrict__ hop_coef, int n) {
    int i = blockIdx.x * blockDim.x + threadIdx.x;
    if (i < n) g_cnt[i] = 0;
    if (blockIdx.x == 0) {
        if (threadIdx.x < 256) { g_st1[threadIdx.x] = 0.f; g_st2[threadIdx.x] = 0.f; }
        if (threadIdx.x == 0) {
            float v[KH];
            float m = -1e30f;
            for (int q = 0; q < KH; q++) { v[q] = hop_coef[q]; m = fmaxf(m, v[q]); }
            float s = 0.f;
            for (int q = 0; q < KH; q++) { v[q] = expf(v[q] - m); s += v[q]; }
            float inv = 1.f / s;
            for (int q = 0; q < KH; q++) g_hopw[q] = v[q] * inv;
        }
    }
}

// ---------------- CSR build ----------------
__global__ void k_hist(const int* __restrict__ ei, const int* __restrict__ ew, int E) {
    int e = blockIdx.x * blockDim.x + threadIdx.x;
    if (e >= E) return;
    int d = ew[e];
    if (d < 1 || d > KH) return;
    atomicAdd(&g_cnt[ei[e]], 1);
}

__global__ void k_scan1(int n) {   // 1024 threads/block, Hillis-Steele
    __shared__ int sh[1024];
    int i = blockIdx.x * 1024 + threadIdx.x;
    int v = (i < n) ? g_cnt[i] : 0;
    sh[threadIdx.x] = v;
    __syncthreads();
    for (int off = 1; off < 1024; off <<= 1) {
        int t = (threadIdx.x >= off) ? sh[threadIdx.x - off] : 0;
        __syncthreads();
        sh[threadIdx.x] += t;
        __syncthreads();
    }
    if (i < n) g_rs[i] = sh[threadIdx.x] - v;        // exclusive
    if (threadIdx.x == 1023) g_bsum[blockIdx.x] = sh[1023];
}

__global__ void k_scan2(int nb) {  // one block, parallel scan over block sums
    __shared__ int sh[NBMAX];
    int t = threadIdx.x;
    int v = (t < nb) ? g_bsum[t] : 0;
    sh[t] = v;
    __syncthreads();
    #pragma unroll
    for (int off = 1; off < NBMAX; off <<= 1) {
        int u = (t >= off) ? sh[t - off] : 0;
        __syncthreads();
        sh[t] += u;
        __syncthreads();
    }
    if (t < nb) g_boff[t] = sh[t] - v;               // exclusive
}

__global__ void k_scan3(int n) {
    int i = blockIdx.x * 1024 + threadIdx.x;
    if (i < n) {
        int s = g_rs[i] + g_boff[blockIdx.x];
        g_rs[i] = s;
        g_cur[i] = s;
    }
}

__global__ void k_edges(const int* __restrict__ ei, const int* __restrict__ ew, int E) {
    int e = blockIdx.x * blockDim.x + threadIdx.x;
    if (e >= E) return;
    int d = ew[e];
    if (d < 1 || d > KH) return;
    int r = ei[e];
    int c = ei[E + e];
    float w = g_hopw[d - 1];
    int pos = atomicAdd(&g_cur[r], 1);
    g_epack[pos] = ((u64)__float_as_uint(w) << 32) | (unsigned)c;
}

// ---------------- aggregate: warp per node, h = x[node] + sum(w * x[col]) ----------------
__global__ void k_aggr(const float4* __restrict__ x4, int n) {
    int node = (blockIdx.x * blockDim.x + threadIdx.x) >> 5;
    int lane = threadIdx.x & 31;
    if (node >= n) return;
    int s = g_rs[node], e = g_cur[node];
    float4 acc = __ldg(&x4[(size_t)node * 32 + lane]);
    for (int base = s; base < e; base += 32) {
        int m = min(32, e - base);
        u64 p = (lane < m) ? g_epack[base + lane] : 0ULL;
        #pragma unroll 4
        for (int j = 0; j < 32; j++) {
            if (j >= m) break;
            u64 pj = __shfl_sync(0xffffffffu, p, j);
            int c = (int)(unsigned)pj;
            float w = __uint_as_float((unsigned)(pj >> 32));
            float4 v = __ldg(&x4[(size_t)c * 32 + lane]);
            acc.x = fmaf(w, v.x, acc.x);
            acc.y = fmaf(w, v.y, acc.y);
            acc.z = fmaf(w, v.z, acc.z);
            acc.w = fmaf(w, v.w, acc.w);
        }
    }
    ((float4*)g_h)[(size_t)node * 32 + lane] = acc;
}

// ---------------- GEMM + fused BN-stats epilogue (R12 + prefetch pipeline) ----------------
// PHASE 1: A = g_h, Y = g_y, stats -> g_st1
// PHASE 2: A = relu(a1*g_y + c1), Y = OutY, stats -> g_st2
// Static tile schedule; next tile's A-fragment is LDG'd into registers
// DURING the current tile's mainloop (latency hidden).
template <int PHASE>
__global__ void __launch_bounds__(256) k_gemm(const float* __restrict__ W,
                                              float* __restrict__ OutY,
                                              int n, int ntiles) {
    const float* A = (PHASE == 1) ? g_h : g_y;
    float* Y       = (PHASE == 1) ? g_y : OutY;

    __shared__ __align__(16) float Ws[FDIM * 128];   // [k][c]  64 KB
    __shared__ __align__(16) float At[FDIM * 64];    // [k][r]  32 KB (transposed)
    __shared__ float sh_st[256];

    int tid = threadIdx.x;
    int tc = tid & 31, tr = tid >> 5;
    sh_st[tid] = 0.f;

    const float4* W4 = (const float4*)W;
    float4* Ws4 = (float4*)Ws;
    #pragma unroll 4
    for (int i = tid; i < FDIM * 32; i += 256) Ws4[i] = W4[i];

    int sc4 = (tc & 3) + 4 * tr;          // float4 column group, loop-invariant
    int sr  = tc >> 2;                    // row base 0..7
    float4 a1v, c1v;
    if (PHASE == 2) {
        a1v = __ldg(&((const float4*)g_a1)[sc4]);
        c1v = __ldg(&((const float4*)g_c1)[sc4]);
    }
    const float4* A4 = (const float4*)A;
    int r0 = tr * 8;
    int stride = gridDim.x;

    // prefetch first tile's fragment
    float4 v[8];
    int t = blockIdx.x;
    #pragma unroll
    for (int j = 0; j < 8; j++) {
        int grow = t * 64 + sr + 8 * j;
        v[j] = (t < ntiles && grow < n) ? A4[(size_t)grow * 32 + sc4]
                                        : make_float4(0.f, 0.f, 0.f, 0.f);
    }

    for (; t < ntiles; t += stride) {
        int row0 = t * 64;

        // store prefetched fragment into At (with phase-2 transform)
        #pragma unroll
        for (int j = 0; j < 8; j++) {
            float4 w = v[j];
            if (PHASE == 2) {
                w.x = fmaxf(fmaf(a1v.x, w.x, c1v.x), 0.f);
                w.y = fmaxf(fmaf(a1v.y, w.y, c1v.y), 0.f);
                w.z = fmaxf(fmaf(a1v.z, w.z, c1v.z), 0.f);
                w.w = fmaxf(fmaf(a1v.w, w.w, c1v.w), 0.f);
            }
            int r = sr + 8 * j;
            int k0 = sc4 * 4;
            At[(k0 + 0) * 64 + r] = w.x;
            At[(k0 + 1) * 64 + r] = w.y;
            At[(k0 + 2) * 64 + r] = w.z;
            At[(k0 + 3) * 64 + r] = w.w;
        }
        __syncthreads();

        // issue next tile's LDGs now; they fly behind the mainloop
        int tn = t + stride;
        #pragma unroll
        for (int j = 0; j < 8; j++) {
            int grow = tn * 64 + sr + 8 * j;
            v[j] = (tn < ntiles && grow < n) ? A4[(size_t)grow * 32 + sc4]
                                             : make_float4(0.f, 0.f, 0.f, 0.f);
        }

        u64 acc[4][4];
        #pragma unroll
        for (int p = 0; p < 4; p++)
            #pragma unroll
            for (int c = 0; c < 4; c++) acc[p][c] = 0ULL;

        #pragma unroll 4
        for (int k = 0; k < FDIM; k++) {
            float4 wv = Ws4[k * 32 + tc];
            u64 w0 = pk2(wv.x, wv.x);
            u64 w1 = pk2(wv.y, wv.y);
            u64 w2 = pk2(wv.z, wv.z);
            u64 w3 = pk2(wv.w, wv.w);
            const ulonglong2* ak = (const ulonglong2*)&At[k * 64 + r0];
            ulonglong2 q01 = ak[0];
            ulonglong2 q23 = ak[1];
            u64 a0 = q01.x, a1 = q01.y, a2 = q23.x, a3 = q23.y;
            FMA2(acc[0][0], a0, w0); FMA2(acc[0][1], a0, w1);
            FMA2(acc[0][2], a0, w2); FMA2(acc[0][3], a0, w3);
            FMA2(acc[1][0], a1, w0); FMA2(acc[1][1], a1, w1);
            FMA2(acc[1][2], a1, w2); FMA2(acc[1][3], a1, w3);
            FMA2(acc[2][0], a2, w0); FMA2(acc[2][1], a2, w1);
            FMA2(acc[2][2], a2, w2); FMA2(acc[2][3], a2, w3);
            FMA2(acc[3][0], a3, w0); FMA2(acc[3][1], a3, w1);
            FMA2(acc[3][2], a3, w2); FMA2(acc[3][3], a3, w3);
        }

        float cs[4] = {0.f, 0.f, 0.f, 0.f};
        float cq[4] = {0.f, 0.f, 0.f, 0.f};
        #pragma unroll
        for (int p = 0; p < 4; p++) {
            float2 c0 = upk2(acc[p][0]);
            float2 c1 = upk2(acc[p][1]);
            float2 c2 = upk2(acc[p][2]);
            float2 c3 = upk2(acc[p][3]);
            int r_lo = row0 + r0 + 2 * p;
            int r_hi = r_lo + 1;
            if (r_lo < n) {
                float4 o = make_float4(c0.x, c1.x, c2.x, c3.x);
                ((float4*)Y)[(size_t)r_lo * 32 + tc] = o;
                cs[0] += o.x; cs[1] += o.y; cs[2] += o.z; cs[3] += o.w;
                cq[0] += o.x * o.x; cq[1] += o.y * o.y;
                cq[2] += o.z * o.z; cq[3] += o.w * o.w;
            }
            if (r_hi < n) {
                float4 o = make_float4(c0.y, c1.y, c2.y, c3.y);
                ((float4*)Y)[(size_t)r_hi * 32 + tc] = o;
                cs[0] += o.x; cs[1] += o.y; cs[2] += o.z; cs[3] += o.w;
                cq[0] += o.x * o.x; cq[1] += o.y * o.y;
                cq[2] += o.z * o.z; cq[3] += o.w * o.w;
            }
        }
        #pragma unroll
        for (int c = 0; c < 4; c++) {
            atomicAdd(&sh_st[tc * 4 + c], cs[c]);
            atomicAdd(&sh_st[128 + tc * 4 + c], cq[c]);
        }
        __syncthreads();   // At consumed before next store; sh_st coherent
    }

    float* gst = (PHASE == 1) ? g_st1 : g_st2;
    atomicAdd(&gst[tid], sh_st[tid]);
}

// ---------------- BN finalize ----------------
template <int PHASE>
__global__ void k_bnfin(const float* __restrict__ gamma,
                        const float* __restrict__ beta, float invN) {
    int i = threadIdx.x;
    const float* st = (PHASE == 1) ? g_st1 : g_st2;
    float mean = st[i] * invN;
    float var = st[i + 128] * invN - mean * mean;
    float s = gamma[i] * rsqrtf(var + BN_EPS);
    if (PHASE == 1) { g_a1[i] = s; g_c1[i] = beta[i] - mean * s; }
    else            { g_a2[i] = s; g_c2[i] = beta[i] - mean * s; }
}

// ---------------- final BN2 + ReLU in place on d_out ----------------
__global__ void k_final(float4* __restrict__ y, int n4) {
    for (int i = blockIdx.x * blockDim.x + threadIdx.x; i < n4;
         i += gridDim.x * blockDim.x) {
        int c4 = i & 31;
        float4 a = __ldg(&((const float4*)g_a2)[c4]);
        float4 b = __ldg(&((const float4*)g_c2)[c4]);
        float4 v = y[i];
        v.x = fmaxf(fmaf(a.x, v.x, b.x), 0.f);
        v.y = fmaxf(fmaf(a.y, v.y, b.y), 0.f);
        v.z = fmaxf(fmaf(a.z, v.z, b.z), 0.f);
        v.w = fmaxf(fmaf(a.w, v.w, b.w), 0.f);
        y[i] = v;
    }
}

// ---------------- launcher ----------------
extern "C" void kernel_launch(void* const* d_in, const int* in_sizes, int n_in,
                              void* d_out, int out_size) {
    const float* x    = (const float*)d_in[0];   // [N,128]
    const int*   ei   = (const int*)  d_in[1];   // [2,E]
    const int*   ew   = (const int*)  d_in[2];   // [E]
    const float* hop  = (const float*)d_in[3];   // [5]
    const float* W1   = (const float*)d_in[4];   // [128,128]
    const float* g1   = (const float*)d_in[6];
    const float* be1  = (const float*)d_in[7];
    const float* W2   = (const float*)d_in[8];
    const float* g2   = (const float*)d_in[10];
    const float* be2  = (const float*)d_in[11];
    float* out = (float*)d_out;

    int n = in_sizes[0] / FDIM;   // 100000
    int E = in_sizes[2];          // 1600000
    int n4 = n * 32;
    float invN = 1.f / (float)n;
    int nb = (n + 1023) / 1024;   // scan blocks (98)

    k_prep0<<<(n + 255) / 256, 256>>>(hop, n);
    k_hist<<<(E + 255) / 256, 256>>>(ei, ew, E);
    k_scan1<<<nb, 1024>>>(n);
    k_scan2<<<1, NBMAX>>>(nb);
    k_scan3<<<nb, 1024>>>(n);
    k_edges<<<(E + 255) / 256, 256>>>(ei, ew, E);
    k_aggr<<<(n * 32 + 255) / 256, 256>>>((const float4*)x, n);

    int ntiles = (n + 63) / 64;                  // 1563
    int gblocks = ntiles < 296 ? ntiles : 296;   // 2 blocks/SM
    k_gemm<1><<<gblocks, 256>>>(W1, nullptr, n, ntiles);
    k_bnfin<1><<<1, 128>>>(g1, be1, invN);
    k_gemm<2><<<gblocks, 256>>>(W2, out, n, ntiles);
    k_bnfin<2><<<1, 128>>>(g2, be2, invN);
    k_final<<<2048, 256>>>((float4*)out, n4);
}

// round 15
// speedup vs baseline: 1.5225x; 1.0065x over previous
#include <cuda_runtime.h>

#define FDIM 128
#define KH 5
#define NMAX 100000
#define EMAX 1600000
#define BN_EPS 1e-5f

typedef unsigned long long u64;

// ---------------- device scratch (static, no allocs) ----------------
__device__ float g_h[(size_t)NMAX * FDIM];   // x + agg  (51.2 MB)
__device__ float g_y[(size_t)NMAX * FDIM];   // y1       (51.2 MB)
__device__ u64   g_epack[EMAX];              // (w_bits<<32)|col per CSR slot
__device__ int   g_cnt[NMAX];                // per-node in-degree
__device__ int   g_rs[NMAX];                 // CSR row start
__device__ int   g_cur[NMAX];                // fill cursor -> row end
__device__ int   g_alloc;                    // CSR region allocator
__device__ float g_hopw[8];
__device__ float g_st1[256];                 // [0:128) colsum, [128:256) colsumsq
__device__ float g_st2[256];

// ---------------- f32x2 helpers ----------------
__device__ __forceinline__ u64 pk2(float lo, float hi) {
    u64 r;
    asm("mov.b64 %0, {%1, %2};" : "=l"(r) : "f"(lo), "f"(hi));
    return r;
}
__device__ __forceinline__ float2 upk2(u64 v) {
    float2 r;
    asm("mov.b64 {%0, %1}, %2;" : "=f"(r.x), "=f"(r.y) : "l"(v));
    return r;
}
#define FMA2(d, a, b) asm("fma.rn.f32x2 %0, %1, %2, %0;" : "+l"(d) : "l"(a), "l"(b))

// ---------------- prep: zero cnt + stats + allocator + softmax ----------------
__global__ void k_prep0(const float* __restrict__ hop_coef, int n) {
    int i = blockIdx.x * blockDim.x + threadIdx.x;
    if (i < n) g_cnt[i] = 0;
    if (blockIdx.x == 0) {
        if (threadIdx.x < 256) { g_st1[threadIdx.x] = 0.f; g_st2[threadIdx.x] = 0.f; }
        if (threadIdx.x == 0) {
            g_alloc = 0;
            float v[KH];
            float m = -1e30f;
            for (int q = 0; q < KH; q++) { v[q] = hop_coef[q]; m = fmaxf(m, v[q]); }
            float s = 0.f;
            for (int q = 0; q < KH; q++) { v[q] = expf(v[q] - m); s += v[q]; }
            float inv = 1.f / s;
            for (int q = 0; q < KH; q++) g_hopw[q] = v[q] * inv;
        }
    }
}

// ---------------- CSR build ----------------
__global__ void k_hist(const int* __restrict__ ei, const int* __restrict__ ew, int E) {
    int e = blockIdx.x * blockDim.x + threadIdx.x;
    if (e >= E) return;
    int d = ew[e];
    if (d < 1 || d > KH) return;
    atomicAdd(&g_cnt[ei[e]], 1);
}

// One-kernel CSR region allocation: warp shfl-scan + one atomicAdd per warp.
// Region ORDER is irrelevant for correctness (disjointness is all aggr needs).
__global__ void k_alloc(int n) {
    int i = blockIdx.x * blockDim.x + threadIdx.x;
    int lane = threadIdx.x & 31;
    int v = (i < n) ? g_cnt[i] : 0;
    int pfx = v;
    #pragma unroll
    for (int off = 1; off < 32; off <<= 1) {
        int t = __shfl_up_sync(0xffffffffu, pfx, off);
        if (lane >= off) pfx += t;
    }
    int tot = __shfl_sync(0xffffffffu, pfx, 31);
    int base = 0;
    if (lane == 0) base = atomicAdd(&g_alloc, tot);
    base = __shfl_sync(0xffffffffu, base, 0);
    int s = base + pfx - v;
    if (i < n) { g_rs[i] = s; g_cur[i] = s; }
}

__global__ void k_edges(const int* __restrict__ ei, const int* __restrict__ ew, int E) {
    int e = blockIdx.x * blockDim.x + threadIdx.x;
    if (e >= E) return;
    int d = ew[e];
    if (d < 1 || d > KH) return;
    int r = ei[e];
    int c = ei[E + e];
    float w = g_hopw[d - 1];
    int pos = atomicAdd(&g_cur[r], 1);
    g_epack[pos] = ((u64)__float_as_uint(w) << 32) | (unsigned)c;
}

// ---------------- aggregate: warp per node, h = x[node] + sum(w * x[col]) ----------------
__global__ void k_aggr(const float4* __restrict__ x4, int n) {
    int node = (blockIdx.x * blockDim.x + threadIdx.x) >> 5;
    int lane = threadIdx.x & 31;
    if (node >= n) return;
    int s = g_rs[node], e = g_cur[node];
    float4 acc = __ldg(&x4[(size_t)node * 32 + lane]);
    for (int base = s; base < e; base += 32) {
        int m = min(32, e - base);
        u64 p = (lane < m) ? g_epack[base + lane] : 0ULL;
        #pragma unroll 4
        for (int j = 0; j < 32; j++) {
            if (j >= m) break;
            u64 pj = __shfl_sync(0xffffffffu, p, j);
            int c = (int)(unsigned)pj;
            float w = __uint_as_float((unsigned)(pj >> 32));
            float4 v = __ldg(&x4[(size_t)c * 32 + lane]);
            acc.x = fmaf(w, v.x, acc.x);
            acc.y = fmaf(w, v.y, acc.y);
            acc.z = fmaf(w, v.z, acc.z);
            acc.w = fmaf(w, v.w, acc.w);
        }
    }
    ((float4*)g_h)[(size_t)node * 32 + lane] = acc;
}

// ---------------- GEMM + fused BN-stats epilogue (R14 pipeline, BN1 fold in phase 2) ----------------
// PHASE 1: A = g_h, Y = g_y, stats -> g_st1
// PHASE 2: A = relu(a1*g_y + c1) with a1/c1 computed per block from g_st1, Y = OutY, stats -> g_st2
template <int PHASE>
__global__ void __launch_bounds__(256) k_gemm(const float* __restrict__ W,
                                              const float* __restrict__ gamma,
                                              const float* __restrict__ beta,
                                              float* __restrict__ OutY,
                                              int n, int ntiles, float invN) {
    const float* A = (PHASE == 1) ? g_h : g_y;
    float* Y       = (PHASE == 1) ? g_y : OutY;

    __shared__ __align__(16) float Ws[FDIM * 128];   // [k][c]  64 KB
    __shared__ __align__(16) float At[FDIM * 64];    // [k][r]  32 KB (transposed)
    __shared__ float sh_st[256];
    __shared__ float bn[256];                        // phase-2 BN1 scale/shift

    int tid = threadIdx.x;
    int tc = tid & 31, tr = tid >> 5;
    sh_st[tid] = 0.f;

    const float4* W4 = (const float4*)W;
    float4* Ws4 = (float4*)Ws;
    #pragma unroll 4
    for (int i = tid; i < FDIM * 32; i += 256) Ws4[i] = W4[i];

    if (PHASE == 2 && tid < 128) {
        float mean = g_st1[tid] * invN;
        float var = g_st1[tid + 128] * invN - mean * mean;
        float s = gamma[tid] * rsqrtf(var + BN_EPS);
        bn[tid] = s;
        bn[tid + 128] = beta[tid] - mean * s;
    }

    int sc4 = (tc & 3) + 4 * tr;          // float4 column group, loop-invariant
    int sr  = tc >> 2;                    // row base 0..7
    const float4* A4 = (const float4*)A;
    int r0 = tr * 8;
    int stride = gridDim.x;

    // prefetch first tile's fragment (independent of bn[])
    float4 v[8];
    int t = blockIdx.x;
    #pragma unroll
    for (int j = 0; j < 8; j++) {
        int grow = t * 64 + sr + 8 * j;
        v[j] = (t < ntiles && grow < n) ? A4[(size_t)grow * 32 + sc4]
                                        : make_float4(0.f, 0.f, 0.f, 0.f);
    }
    __syncthreads();   // bn[] + Ws ready

    float4 a1v, c1v;
    if (PHASE == 2) {
        a1v = *(const float4*)&bn[sc4 * 4];
        c1v = *(const float4*)&bn[128 + sc4 * 4];
    }

    for (; t < ntiles; t += stride) {
        int row0 = t * 64;

        #pragma unroll
        for (int j = 0; j < 8; j++) {
            float4 w = v[j];
            if (PHASE == 2) {
                w.x = fmaxf(fmaf(a1v.x, w.x, c1v.x), 0.f);
                w.y = fmaxf(fmaf(a1v.y, w.y, c1v.y), 0.f);
                w.z = fmaxf(fmaf(a1v.z, w.z, c1v.z), 0.f);
                w.w = fmaxf(fmaf(a1v.w, w.w, c1v.w), 0.f);
            }
            int r = sr + 8 * j;
            int k0 = sc4 * 4;
            At[(k0 + 0) * 64 + r] = w.x;
            At[(k0 + 1) * 64 + r] = w.y;
            At[(k0 + 2) * 64 + r] = w.z;
            At[(k0 + 3) * 64 + r] = w.w;
        }
        __syncthreads();

        // issue next tile's LDGs; they fly behind the mainloop
        int tn = t + stride;
        #pragma unroll
        for (int j = 0; j < 8; j++) {
            int grow = tn * 64 + sr + 8 * j;
            v[j] = (tn < ntiles && grow < n) ? A4[(size_t)grow * 32 + sc4]
                                             : make_float4(0.f, 0.f, 0.f, 0.f);
        }

        u64 acc[4][4];
        #pragma unroll
        for (int p = 0; p < 4; p++)
            #pragma unroll
            for (int c = 0; c < 4; c++) acc[p][c] = 0ULL;

        #pragma unroll 4
        for (int k = 0; k < FDIM; k++) {
            float4 wv = Ws4[k * 32 + tc];
            u64 w0 = pk2(wv.x, wv.x);
            u64 w1 = pk2(wv.y, wv.y);
            u64 w2 = pk2(wv.z, wv.z);
            u64 w3 = pk2(wv.w, wv.w);
            const ulonglong2* ak = (const ulonglong2*)&At[k * 64 + r0];
            ulonglong2 q01 = ak[0];
            ulonglong2 q23 = ak[1];
            u64 a0 = q01.x, a1 = q01.y, a2 = q23.x, a3 = q23.y;
            FMA2(acc[0][0], a0, w0); FMA2(acc[0][1], a0, w1);
            FMA2(acc[0][2], a0, w2); FMA2(acc[0][3], a0, w3);
            FMA2(acc[1][0], a1, w0); FMA2(acc[1][1], a1, w1);
            FMA2(acc[1][2], a1, w2); FMA2(acc[1][3], a1, w3);
            FMA2(acc[2][0], a2, w0); FMA2(acc[2][1], a2, w1);
            FMA2(acc[2][2], a2, w2); FMA2(acc[2][3], a2, w3);
            FMA2(acc[3][0], a3, w0); FMA2(acc[3][1], a3, w1);
            FMA2(acc[3][2], a3, w2); FMA2(acc[3][3], a3, w3);
        }

        float cs[4] = {0.f, 0.f, 0.f, 0.f};
        float cq[4] = {0.f, 0.f, 0.f, 0.f};
        #pragma unroll
        for (int p = 0; p < 4; p++) {
            float2 c0 = upk2(acc[p][0]);
            float2 c1 = upk2(acc[p][1]);
            float2 c2 = upk2(acc[p][2]);
            float2 c3 = upk2(acc[p][3]);
            int r_lo = row0 + r0 + 2 * p;
            int r_hi = r_lo + 1;
            if (r_lo < n) {
                float4 o = make_float4(c0.x, c1.x, c2.x, c3.x);
                ((float4*)Y)[(size_t)r_lo * 32 + tc] = o;
                cs[0] += o.x; cs[1] += o.y; cs[2] += o.z; cs[3] += o.w;
                cq[0] += o.x * o.x; cq[1] += o.y * o.y;
                cq[2] += o.z * o.z; cq[3] += o.w * o.w;
            }
            if (r_hi < n) {
                float4 o = make_float4(c0.y, c1.y, c2.y, c3.y);
                ((float4*)Y)[(size_t)r_hi * 32 + tc] = o;
                cs[0] += o.x; cs[1] += o.y; cs[2] += o.z; cs[3] += o.w;
                cq[0] += o.x * o.x; cq[1] += o.y * o.y;
                cq[2] += o.z * o.z; cq[3] += o.w * o.w;
            }
        }
        #pragma unroll
        for (int c = 0; c < 4; c++) {
            atomicAdd(&sh_st[tc * 4 + c], cs[c]);
            atomicAdd(&sh_st[128 + tc * 4 + c], cq[c]);
        }
        __syncthreads();
    }

    float* gst = (PHASE == 1) ? g_st1 : g_st2;
    atomicAdd(&gst[tid], sh_st[tid]);
}

// ---------------- final: BN2 computed inline + ReLU in place on d_out ----------------
__global__ void k_final(float4* __restrict__ y,
                        const float* __restrict__ gamma,
                        const float* __restrict__ beta,
                        float invN, int n4) {
    int idx0 = blockIdx.x * blockDim.x + threadIdx.x;
    int c4 = idx0 & 31;   // constant per thread: stride (2048*256) divisible by 32
    float4 a, b;
    {
        float* pa = (float*)&a;
        float* pb = (float*)&b;
        #pragma unroll
        for (int q = 0; q < 4; q++) {
            int col = c4 * 4 + q;
            float mean = g_st2[col] * invN;
            float var = g_st2[col + 128] * invN - mean * mean;
            float s = __ldg(&gamma[col]) * rsqrtf(var + BN_EPS);
            pa[q] = s;
            pb[q] = __ldg(&beta[col]) - mean * s;
        }
    }
    for (int i = idx0; i < n4; i += gridDim.x * blockDim.x) {
        float4 v = y[i];
        v.x = fmaxf(fmaf(a.x, v.x, b.x), 0.f);
        v.y = fmaxf(fmaf(a.y, v.y, b.y), 0.f);
        v.z = fmaxf(fmaf(a.z, v.z, b.z), 0.f);
        v.w = fmaxf(fmaf(a.w, v.w, b.w), 0.f);
        y[i] = v;
    }
}

// ---------------- launcher ----------------
extern "C" void kernel_launch(void* const* d_in, const int* in_sizes, int n_in,
                              void* d_out, int out_size) {
    const float* x    = (const float*)d_in[0];   // [N,128]
    const int*   ei   = (const int*)  d_in[1];   // [2,E]
    const int*   ew   = (const int*)  d_in[2];   // [E]
    const float* hop  = (const float*)d_in[3];   // [5]
    const float* W1   = (const float*)d_in[4];   // [128,128]
    const float* g1   = (const float*)d_in[6];
    const float* be1  = (const float*)d_in[7];
    const float* W2   = (const float*)d_in[8];
    const float* g2   = (const float*)d_in[10];
    const float* be2  = (const float*)d_in[11];
    float* out = (float*)d_out;

    int n = in_sizes[0] / FDIM;   // 100000
    int E = in_sizes[2];          // 1600000
    int n4 = n * 32;
    float invN = 1.f / (float)n;

    k_prep0<<<(n + 255) / 256, 256>>>(hop, n);
    k_hist<<<(E + 255) / 256, 256>>>(ei, ew, E);
    k_alloc<<<(n + 255) / 256, 256>>>(n);
    k_edges<<<(E + 255) / 256, 256>>>(ei, ew, E);
    k_aggr<<<(n * 32 + 255) / 256, 256>>>((const float4*)x, n);

    int ntiles = (n + 63) / 64;                  // 1563
    int gblocks = ntiles < 296 ? ntiles : 296;   // 2 blocks/SM
    k_gemm<1><<<gblocks, 256>>>(W1, g1, be1, nullptr, n, ntiles, invN);
    k_gemm<2><<<gblocks, 256>>>(W2, g1, be1, out, n, ntiles, invN);
    k_final<<<2048, 256>>>((float4*)out, g2, be2, invN, n4);
}

// round 16
// speedup vs baseline: 1.6162x; 1.0615x over previous
#include <cuda_runtime.h>

#define FDIM 128
#define KH 5
#define NMAX 100000
#define EMAX 1600000
#define BN_EPS 1e-5f

typedef unsigned long long u64;
typedef unsigned int u32;

// ---------------- device scratch (static, no allocs) ----------------
__device__ float g_h[(size_t)NMAX * FDIM];   // x + agg  (51.2 MB)
__device__ float g_y[(size_t)NMAX * FDIM];   // y1       (51.2 MB)
__device__ u32   g_epack[EMAX];              // col | (hop<<27) per CSR slot (6.4 MB)
__device__ int   g_cnt[NMAX];                // per-node in-degree
__device__ int   g_rs[NMAX];                 // CSR row start
__device__ int   g_cur[NMAX];                // fill cursor -> row end
__device__ int   g_alloc;                    // CSR region allocator
__device__ float g_hopw[8];
__device__ float g_st1[256];                 // [0:128) colsum, [128:256) colsumsq
__device__ float g_st2[256];

// ---------------- f32x2 helpers ----------------
__device__ __forceinline__ u64 pk2(float lo, float hi) {
    u64 r;
    asm("mov.b64 %0, {%1, %2};" : "=l"(r) : "f"(lo), "f"(hi));
    return r;
}
__device__ __forceinline__ float2 upk2(u64 v) {
    float2 r;
    asm("mov.b64 {%0, %1}, %2;" : "=f"(r.x), "=f"(r.y) : "l"(v));
    return r;
}
#define FMA2(d, a, b) asm("fma.rn.f32x2 %0, %1, %2, %0;" : "+l"(d) : "l"(a), "l"(b))

// ---------------- prep: zero cnt + stats + allocator + softmax ----------------
__global__ void k_prep0(const float* __restrict__ hop_coef, int n) {
    int i = blockIdx.x * blockDim.x + threadIdx.x;
    if (i < n) g_cnt[i] = 0;
    if (blockIdx.x == 0) {
        if (threadIdx.x < 256) { g_st1[threadIdx.x] = 0.f; g_st2[threadIdx.x] = 0.f; }
        if (threadIdx.x == 0) {
            g_alloc = 0;
            float v[KH];
            float m = -1e30f;
            for (int q = 0; q < KH; q++) { v[q] = hop_coef[q]; m = fmaxf(m, v[q]); }
            float s = 0.f;
            for (int q = 0; q < KH; q++) { v[q] = expf(v[q] - m); s += v[q]; }
            float inv = 1.f / s;
            for (int q = 0; q < KH; q++) g_hopw[q] = v[q] * inv;
        }
    }
}

// ---------------- CSR build ----------------
__global__ void k_hist(const int* __restrict__ ei, const int* __restrict__ ew, int E) {
    int e = blockIdx.x * blockDim.x + threadIdx.x;
    if (e >= E) return;
    int d = ew[e];
    if (d < 1 || d > KH) return;
    atomicAdd(&g_cnt[ei[e]], 1);
}

// One-kernel CSR region allocation: warp shfl-scan + one atomicAdd per warp.
__global__ void k_alloc(int n) {
    int i = blockIdx.x * blockDim.x + threadIdx.x;
    int lane = threadIdx.x & 31;
    int v = (i < n) ? g_cnt[i] : 0;
    int pfx = v;
    #pragma unroll
    for (int off = 1; off < 32; off <<= 1) {
        int t = __shfl_up_sync(0xffffffffu, pfx, off);
        if (lane >= off) pfx += t;
    }
    int tot = __shfl_sync(0xffffffffu, pfx, 31);
    int base = 0;
    if (lane == 0) base = atomicAdd(&g_alloc, tot);
    base = __shfl_sync(0xffffffffu, base, 0);
    int s = base + pfx - v;
    if (i < n) { g_rs[i] = s; g_cur[i] = s; }
}

// 4-byte edge records: col (17 bits used) | hop index << 27
__global__ void k_edges(const int* __restrict__ ei, const int* __restrict__ ew, int E) {
    int e = blockIdx.x * blockDim.x + threadIdx.x;
    if (e >= E) return;
    int d = ew[e];
    if (d < 1 || d > KH) return;
    int r = ei[e];
    u32 c = (u32)ei[E + e];
    int pos = atomicAdd(&g_cur[r], 1);
    g_epack[pos] = c | ((u32)(d - 1) << 27);
}

// ---------------- aggregate: warp per node, h = x[node] + sum(w * x[col]) ----------------
__global__ void k_aggr(const float4* __restrict__ x4, int n) {
    int node = (blockIdx.x * blockDim.x + threadIdx.x) >> 5;
    int lane = threadIdx.x & 31;
    if (node >= n) return;
    int s = g_rs[node], e = g_cur[node];
    float4 acc = __ldg(&x4[(size_t)node * 32 + lane]);
    for (int base = s; base < e; base += 32) {
        int m = min(32, e - base);
        u32 p = (lane < m) ? g_epack[base + lane] : 0u;
        #pragma unroll 4
        for (int j = 0; j < 32; j++) {
            if (j >= m) break;
            u32 pj = __shfl_sync(0xffffffffu, p, j);
            int c = (int)(pj & 0x07FFFFFFu);
            float w = g_hopw[pj >> 27];
            float4 v = __ldg(&x4[(size_t)c * 32 + lane]);
            acc.x = fmaf(w, v.x, acc.x);
            acc.y = fmaf(w, v.y, acc.y);
            acc.z = fmaf(w, v.z, acc.z);
            acc.w = fmaf(w, v.w, acc.w);
        }
    }
    ((float4*)g_h)[(size_t)node * 32 + lane] = acc;
}

// ---------------- GEMM + fused BN-stats epilogue (R14 pipeline, BN1 fold in phase 2) ----------------
template <int PHASE>
__global__ void __launch_bounds__(256) k_gemm(const float* __restrict__ W,
                                              const float* __restrict__ gamma,
                                              const float* __restrict__ beta,
                                              float* __restrict__ OutY,
                                              int n, int ntiles, float invN) {
    const float* A = (PHASE == 1) ? g_h : g_y;
    float* Y       = (PHASE == 1) ? g_y : OutY;

    __shared__ __align__(16) float Ws[FDIM * 128];   // [k][c]  64 KB
    __shared__ __align__(16) float At[FDIM * 64];    // [k][r]  32 KB (transposed)
    __shared__ float sh_st[256];
    __shared__ float bn[256];                        // phase-2 BN1 scale/shift

    int tid = threadIdx.x;
    int tc = tid & 31, tr = tid >> 5;
    sh_st[tid] = 0.f;

    const float4* W4 = (const float4*)W;
    float4* Ws4 = (float4*)Ws;
    #pragma unroll 4
    for (int i = tid; i < FDIM * 32; i += 256) Ws4[i] = W4[i];

    if (PHASE == 2 && tid < 128) {
        float mean = g_st1[tid] * invN;
        float var = g_st1[tid + 128] * invN - mean * mean;
        float s = gamma[tid] * rsqrtf(var + BN_EPS);
        bn[tid] = s;
        bn[tid + 128] = beta[tid] - mean * s;
    }

    int sc4 = (tc & 3) + 4 * tr;          // float4 column group, loop-invariant
    int sr  = tc >> 2;                    // row base 0..7
    const float4* A4 = (const float4*)A;
    int r0 = tr * 8;
    int stride = gridDim.x;

    // prefetch first tile's fragment (independent of bn[])
    float4 v[8];
    int t = blockIdx.x;
    #pragma unroll
    for (int j = 0; j < 8; j++) {
        int grow = t * 64 + sr + 8 * j;
        v[j] = (t < ntiles && grow < n) ? A4[(size_t)grow * 32 + sc4]
                                        : make_float4(0.f, 0.f, 0.f, 0.f);
    }
    __syncthreads();   // bn[] + Ws ready

    float4 a1v, c1v;
    if (PHASE == 2) {
        a1v = *(const float4*)&bn[sc4 * 4];
        c1v = *(const float4*)&bn[128 + sc4 * 4];
    }

    for (; t < ntiles; t += stride) {
        int row0 = t * 64;

        #pragma unroll
        for (int j = 0; j < 8; j++) {
            float4 w = v[j];
            if (PHASE == 2) {
                w.x = fmaxf(fmaf(a1v.x, w.x, c1v.x), 0.f);
                w.y = fmaxf(fmaf(a1v.y, w.y, c1v.y), 0.f);
                w.z = fmaxf(fmaf(a1v.z, w.z, c1v.z), 0.f);
                w.w = fmaxf(fmaf(a1v.w, w.w, c1v.w), 0.f);
            }
            int r = sr + 8 * j;
            int k0 = sc4 * 4;
            At[(k0 + 0) * 64 + r] = w.x;
            At[(k0 + 1) * 64 + r] = w.y;
            At[(k0 + 2) * 64 + r] = w.z;
            At[(k0 + 3) * 64 + r] = w.w;
        }
        __syncthreads();

        // issue next tile's LDGs; they fly behind the mainloop
        int tn = t + stride;
        #pragma unroll
        for (int j = 0; j < 8; j++) {
            int grow = tn * 64 + sr + 8 * j;
            v[j] = (tn < ntiles && grow < n) ? A4[(size_t)grow * 32 + sc4]
                                             : make_float4(0.f, 0.f, 0.f, 0.f);
        }

        u64 acc[4][4];
        #pragma unroll
        for (int p = 0; p < 4; p++)
            #pragma unroll
            for (int c = 0; c < 4; c++) acc[p][c] = 0ULL;

        #pragma unroll 4
        for (int k = 0; k < FDIM; k++) {
            float4 wv = Ws4[k * 32 + tc];
            u64 w0 = pk2(wv.x, wv.x);
            u64 w1 = pk2(wv.y, wv.y);
            u64 w2 = pk2(wv.z, wv.z);
            u64 w3 = pk2(wv.w, wv.w);
            const ulonglong2* ak = (const ulonglong2*)&At[k * 64 + r0];
            ulonglong2 q01 = ak[0];
            ulonglong2 q23 = ak[1];
            u64 a0 = q01.x, a1 = q01.y, a2 = q23.x, a3 = q23.y;
            FMA2(acc[0][0], a0, w0); FMA2(acc[0][1], a0, w1);
            FMA2(acc[0][2], a0, w2); FMA2(acc[0][3], a0, w3);
            FMA2(acc[1][0], a1, w0); FMA2(acc[1][1], a1, w1);
            FMA2(acc[1][2], a1, w2); FMA2(acc[1][3], a1, w3);
            FMA2(acc[2][0], a2, w0); FMA2(acc[2][1], a2, w1);
            FMA2(acc[2][2], a2, w2); FMA2(acc[2][3], a2, w3);
            FMA2(acc[3][0], a3, w0); FMA2(acc[3][1], a3, w1);
            FMA2(acc[3][2], a3, w2); FMA2(acc[3][3], a3, w3);
        }

        float cs[4] = {0.f, 0.f, 0.f, 0.f};
        float cq[4] = {0.f, 0.f, 0.f, 0.f};
        #pragma unroll
        for (int p = 0; p < 4; p++) {
            float2 c0 = upk2(acc[p][0]);
            float2 c1 = upk2(acc[p][1]);
            float2 c2 = upk2(acc[p][2]);
            float2 c3 = upk2(acc[p][3]);
            int r_lo = row0 + r0 + 2 * p;
            int r_hi = r_lo + 1;
            if (r_lo < n) {
                float4 o = make_float4(c0.x, c1.x, c2.x, c3.x);
                ((float4*)Y)[(size_t)r_lo * 32 + tc] = o;
                cs[0] += o.x; cs[1] += o.y; cs[2] += o.z; cs[3] += o.w;
                cq[0] += o.x * o.x; cq[1] += o.y * o.y;
                cq[2] += o.z * o.z; cq[3] += o.w * o.w;
            }
            if (r_hi < n) {
                float4 o = make_float4(c0.y, c1.y, c2.y, c3.y);
                ((float4*)Y)[(size_t)r_hi * 32 + tc] = o;
                cs[0] += o.x; cs[1] += o.y; cs[2] += o.z; cs[3] += o.w;
                cq[0] += o.x * o.x; cq[1] += o.y * o.y;
                cq[2] += o.z * o.z; cq[3] += o.w * o.w;
            }
        }
        #pragma unroll
        for (int c = 0; c < 4; c++) {
            atomicAdd(&sh_st[tc * 4 + c], cs[c]);
            atomicAdd(&sh_st[128 + tc * 4 + c], cq[c]);
        }
        __syncthreads();
    }

    float* gst = (PHASE == 1) ? g_st1 : g_st2;
    atomicAdd(&gst[tid], sh_st[tid]);
}

// ---------------- final: BN2 computed inline + ReLU in place on d_out ----------------
__global__ void k_final(float4* __restrict__ y,
                        const float* __restrict__ gamma,
                        const float* __restrict__ beta,
                        float invN, int n4) {
    int idx0 = blockIdx.x * blockDim.x + threadIdx.x;
    int c4 = idx0 & 31;
    float4 a, b;
    {
        float* pa = (float*)&a;
        float* pb = (float*)&b;
        #pragma unroll
        for (int q = 0; q < 4; q++) {
            int col = c4 * 4 + q;
            float mean = g_st2[col] * invN;
            float var = g_st2[col + 128] * invN - mean * mean;
            float s = __ldg(&gamma[col]) * rsqrtf(var + BN_EPS);
            pa[q] = s;
            pb[q] = __ldg(&beta[col]) - mean * s;
        }
    }
    for (int i = idx0; i < n4; i += gridDim.x * blockDim.x) {
        float4 v = y[i];
        v.x = fmaxf(fmaf(a.x, v.x, b.x), 0.f);
        v.y = fmaxf(fmaf(a.y, v.y, b.y), 0.f);
        v.z = fmaxf(fmaf(a.z, v.z, b.z), 0.f);
        v.w = fmaxf(fmaf(a.w, v.w, b.w), 0.f);
        y[i] = v;
    }
}

// ---------------- launcher ----------------
extern "C" void kernel_launch(void* const* d_in, const int* in_sizes, int n_in,
                              void* d_out, int out_size) {
    const float* x    = (const float*)d_in[0];   // [N,128]
    const int*   ei   = (const int*)  d_in[1];   // [2,E]
    const int*   ew   = (const int*)  d_in[2];   // [E]
    const float* hop  = (const float*)d_in[3];   // [5]
    const float* W1   = (const float*)d_in[4];   // [128,128]
    const float* g1   = (const float*)d_in[6];
    const float* be1  = (const float*)d_in[7];
    const float* W2   = (const float*)d_in[8];
    const float* g2   = (const float*)d_in[10];
    const float* be2  = (const float*)d_in[11];
    float* out = (float*)d_out;

    int n = in_sizes[0] / FDIM;   // 100000
    int E = in_sizes[2];          // 1600000
    int n4 = n * 32;
    float invN = 1.f / (float)n;

    k_prep0<<<(n + 255) / 256, 256>>>(hop, n);
    k_hist<<<(E + 255) / 256, 256>>>(ei, ew, E);
    k_alloc<<<(n + 255) / 256, 256>>>(n);
    k_edges<<<(E + 255) / 256, 256>>>(ei, ew, E);
    k_aggr<<<(n * 32 + 255) / 256, 256>>>((const float4*)x, n);

    int ntiles = (n + 63) / 64;                  // 1563
    int gblocks = ntiles < 296 ? ntiles : 296;   // 2 blocks/SM
    k_gemm<1><<<gblocks, 256>>>(W1, g1, be1, nullptr, n, ntiles, invN);
    k_gemm<2><<<gblocks, 256>>>(W2, g1, be1, out, n, ntiles, invN);
    k_final<<<2048, 256>>>((float4*)out, g2, be2, invN, n4);
}